// round 1
// baseline (speedup 1.0000x reference)
#include <cuda_runtime.h>
#include <cuda_bf16.h>

#define N_NODES 50000
#define N_EDGES 800000
#define LATENT 32
#define STEPS 10
#define NEG_SLOPE 0.01f
#define LN_EPS 1e-5f

// ---------------- scratch (device globals; no allocation allowed) ----------------
__device__ float g_h[N_NODES * LATENT];      // node latent
__device__ float g_e[N_EDGES * LATENT];      // edge latent (102 MB)
__device__ float g_hs[N_NODES * LATENT];     // h @ W_src  (per step)
__device__ float g_hd[N_NODES * LATENT];     // h @ W_dst  (per step)
__device__ float g_agg[N_NODES * LATENT];    // scatter accumulator
__device__ float g_cnt[N_NODES];
__device__ float g_inv[N_NODES];

__device__ __forceinline__ float leaky(float v) {
    return v >= 0.f ? v : NEG_SLOPE * v;
}

__device__ __forceinline__ float warp_sum(float v) {
    v += __shfl_xor_sync(0xffffffffu, v, 16);
    v += __shfl_xor_sync(0xffffffffu, v, 8);
    v += __shfl_xor_sync(0xffffffffu, v, 4);
    v += __shfl_xor_sync(0xffffffffu, v, 2);
    v += __shfl_xor_sync(0xffffffffu, v, 1);
    return v;
}

// ---------------- encoders ----------------
__global__ void encode_nodes(const float* __restrict__ x,
                             const float* __restrict__ W,
                             const float* __restrict__ b) {
    int i = blockIdx.x * blockDim.x + threadIdx.x;
    if (i >= N_NODES * 32) return;
    int n = i >> 5, c = i & 31;
    float a = b[c];
#pragma unroll
    for (int k = 0; k < 6; k++) a += x[n * 6 + k] * W[k * 32 + c];
    g_h[i] = leaky(a);
}

__global__ void encode_edges(const float* __restrict__ ea,
                             const float* __restrict__ W,
                             const float* __restrict__ b) {
    int i = blockIdx.x * blockDim.x + threadIdx.x;
    if (i >= N_EDGES * 32) return;
    int e = i >> 5, c = i & 31;
    float a = b[c];
#pragma unroll
    for (int k = 0; k < 3; k++) a += ea[e * 3 + k] * W[k * 32 + c];
    g_e[i] = leaky(a);
}

// ---------------- in-degree ----------------
__global__ void zero_cnt() {
    int i = blockIdx.x * blockDim.x + threadIdx.x;
    if (i < N_NODES) g_cnt[i] = 0.f;
}
__global__ void count_edges(const int* __restrict__ rcv) {
    int i = blockIdx.x * blockDim.x + threadIdx.x;
    if (i < N_EDGES) atomicAdd(&g_cnt[rcv[i]], 1.f);
}
__global__ void make_inv() {
    int i = blockIdx.x * blockDim.x + threadIdx.x;
    if (i < N_NODES) g_inv[i] = 1.f / fmaxf(g_cnt[i], 1.f);
}

// ---------------- per-step: precompute Hs = h@W[32:64], Hd = h@W[64:96]; zero agg ----------------
__global__ void node_pre(const float* __restrict__ eW) {
    __shared__ float ws[64 * 32];  // rows 32..95 of eW
    for (int i = threadIdx.x; i < 64 * 32; i += blockDim.x)
        ws[i] = eW[32 * 32 + i];
    __syncthreads();
    int lane = threadIdx.x & 31;
    int warp = (blockIdx.x * blockDim.x + threadIdx.x) >> 5;
    int nwarps = (gridDim.x * blockDim.x) >> 5;
    for (int n = warp; n < N_NODES; n += nwarps) {
        float hv = g_h[n * 32 + lane];
        float aS = 0.f, aD = 0.f;
#pragma unroll
        for (int k = 0; k < 32; k++) {
            float hk = __shfl_sync(0xffffffffu, hv, k);
            aS += hk * ws[k * 32 + lane];
            aD += hk * ws[(32 + k) * 32 + lane];
        }
        g_hs[n * 32 + lane] = aS;
        g_hd[n * 32 + lane] = aD;
        g_agg[n * 32 + lane] = 0.f;
    }
}

// ---------------- per-step: edge update + fused scatter-add ----------------
__global__ void __launch_bounds__(256) edge_update(
        const float* __restrict__ eW, const float* __restrict__ eb,
        const float* __restrict__ lns, const float* __restrict__ lnb,
        const int* __restrict__ snd, const int* __restrict__ rcv) {
    int lane = threadIdx.x & 31;
    int warp = (blockIdx.x * blockDim.x + threadIdx.x) >> 5;
    int nwarps = (gridDim.x * blockDim.x) >> 5;

    // lane holds column `lane` of W_e (rows 0..31 of eW) in registers
    float w[32];
#pragma unroll
    for (int k = 0; k < 32; k++) w[k] = eW[k * 32 + lane];
    float bias = eb[lane], sc = lns[lane], bi = lnb[lane];

    for (int e = warp; e < N_EDGES; e += nwarps) {
        float ev = g_e[e * 32 + lane];
        int s = snd[e], r = rcv[e];
        float acc0 = bias + g_hs[s * 32 + lane];
        float acc1 = g_hd[r * 32 + lane];
        float acc2 = 0.f, acc3 = 0.f;
#pragma unroll
        for (int k = 0; k < 32; k += 4) {
            acc0 += __shfl_sync(0xffffffffu, ev, k + 0) * w[k + 0];
            acc1 += __shfl_sync(0xffffffffu, ev, k + 1) * w[k + 1];
            acc2 += __shfl_sync(0xffffffffu, ev, k + 2) * w[k + 2];
            acc3 += __shfl_sync(0xffffffffu, ev, k + 3) * w[k + 3];
        }
        float m = leaky((acc0 + acc1) + (acc2 + acc3));
        float mu = warp_sum(m) * (1.f / 32.f);
        float d = m - mu;
        float var = warp_sum(d * d) * (1.f / 32.f);
        float y = d * rsqrtf(var + LN_EPS) * sc + bi;
        float en = ev + y;
        g_e[e * 32 + lane] = en;
        atomicAdd(&g_agg[r * 32 + lane], en);
    }
}

// ---------------- per-step: node update ----------------
__global__ void node_update(const float* __restrict__ nW, const float* __restrict__ nb,
                            const float* __restrict__ lns, const float* __restrict__ lnb) {
    __shared__ float ws[64 * 32];
    for (int i = threadIdx.x; i < 64 * 32; i += blockDim.x) ws[i] = nW[i];
    __syncthreads();
    int lane = threadIdx.x & 31;
    int warp = (blockIdx.x * blockDim.x + threadIdx.x) >> 5;
    int nwarps = (gridDim.x * blockDim.x) >> 5;
    float bias = nb[lane], sc = lns[lane], bi = lnb[lane];
    for (int n = warp; n < N_NODES; n += nwarps) {
        float hv = g_h[n * 32 + lane];
        float av = g_agg[n * 32 + lane] * g_inv[n];
        float acc = bias;
#pragma unroll
        for (int k = 0; k < 32; k++) {
            float a = __shfl_sync(0xffffffffu, hv, k);
            float b2 = __shfl_sync(0xffffffffu, av, k);
            acc += a * ws[k * 32 + lane] + b2 * ws[(32 + k) * 32 + lane];
        }
        float m = leaky(acc);
        float mu = warp_sum(m) * (1.f / 32.f);
        float d = m - mu;
        float var = warp_sum(d * d) * (1.f / 32.f);
        float y = d * rsqrtf(var + LN_EPS) * sc + bi;
        g_h[n * 32 + lane] = hv + y;
    }
}

// ---------------- decoder ----------------
__global__ void decode(const float* __restrict__ W1, const float* __restrict__ b1,
                       const float* __restrict__ W2, const float* __restrict__ b2,
                       float* __restrict__ out) {
    __shared__ float ws[32 * 32];
    for (int i = threadIdx.x; i < 32 * 32; i += blockDim.x) ws[i] = W1[i];
    __syncthreads();
    int lane = threadIdx.x & 31;
    int warp = (blockIdx.x * blockDim.x + threadIdx.x) >> 5;
    int nwarps = (gridDim.x * blockDim.x) >> 5;
    for (int n = warp; n < N_NODES; n += nwarps) {
        float hv = g_h[n * 32 + lane];
        float t = b1[lane];
#pragma unroll
        for (int k = 0; k < 32; k++)
            t += __shfl_sync(0xffffffffu, hv, k) * ws[k * 32 + lane];
        t = leaky(t);
        float r = warp_sum(t * W2[lane]);
        if (lane == 0) out[n] = r + b2[0];
    }
}

// ---------------- launch ----------------
extern "C" void kernel_launch(void* const* d_in, const int* in_sizes, int n_in,
                              void* d_out, int out_size) {
    const float* x   = (const float*)d_in[0];
    const float* ea  = (const float*)d_in[1];
    const int*   snd = (const int*)d_in[2];
    const int*   rcv = (const int*)d_in[3];
    const float* neW = (const float*)d_in[4];
    const float* neb = (const float*)d_in[5];
    const float* eeW = (const float*)d_in[6];
    const float* eeb = (const float*)d_in[7];
    const float* eW  = (const float*)d_in[8];
    const float* eb  = (const float*)d_in[9];
    const float* els = (const float*)d_in[10];
    const float* elb = (const float*)d_in[11];
    const float* nW  = (const float*)d_in[12];
    const float* nb  = (const float*)d_in[13];
    const float* nls = (const float*)d_in[14];
    const float* nlb = (const float*)d_in[15];
    const float* dW1 = (const float*)d_in[16];
    const float* db1 = (const float*)d_in[17];
    const float* dW2 = (const float*)d_in[18];
    const float* db2 = (const float*)d_in[19];
    float* out = (float*)d_out;

    encode_nodes<<<(N_NODES * 32 + 255) / 256, 256>>>(x, neW, neb);
    encode_edges<<<(N_EDGES * 32 + 255) / 256, 256>>>(ea, eeW, eeb);
    zero_cnt<<<(N_NODES + 255) / 256, 256>>>();
    count_edges<<<(N_EDGES + 255) / 256, 256>>>(rcv);
    make_inv<<<(N_NODES + 255) / 256, 256>>>();

    for (int s = 0; s < STEPS; s++) {
        node_pre<<<592, 256>>>(eW + s * 96 * 32);
        edge_update<<<1184, 256>>>(eW + s * 96 * 32, eb + s * 32,
                                   els + s * 32, elb + s * 32, snd, rcv);
        node_update<<<592, 256>>>(nW + s * 64 * 32, nb + s * 32,
                                  nls + s * 32, nlb + s * 32);
    }
    decode<<<592, 256>>>(dW1, db1, dW2, db2, out);
}